// round 2
// baseline (speedup 1.0000x reference)
#include <cuda_runtime.h>
#include <cstdint>

#define Hd    1536
#define FOURH 6144
#define NS    1008   // (T-1)*B = 63*16 sequential steps

// ---------------- static device scratch (no runtime allocation) ----------------
__device__ float g_xpre[(size_t)NS * FOURH];   // layer-0 input projection [1008, 6144]
__device__ float g_h0[2][Hd];                  // ping-pong h for layer 0
__device__ float g_h1[2][Hd];                  // ping-pong h for layer 1
__device__ unsigned int g_bar_count = 0;
__device__ unsigned int g_bar_gen   = 0;

// ---------------- software grid barrier (graph-capturable, all blocks resident) ----
__device__ __forceinline__ void grid_barrier(int G) {
    __syncthreads();
    if (threadIdx.x == 0) {
        __threadfence();
        volatile unsigned int* genp = &g_bar_gen;
        unsigned int gen = *genp;
        unsigned int a = atomicAdd(&g_bar_count, 1u);
        if (a == (unsigned int)(G - 1)) {
            atomicExch(&g_bar_count, 0u);
            __threadfence();
            *genp = gen + 1u;
        } else {
            while (*genp == gen) { }
        }
    }
    __syncthreads();
}

__device__ __forceinline__ float wred(float v) {
    v += __shfl_xor_sync(0xffffffffu, v, 16);
    v += __shfl_xor_sync(0xffffffffu, v, 8);
    v += __shfl_xor_sync(0xffffffffu, v, 4);
    v += __shfl_xor_sync(0xffffffffu, v, 2);
    v += __shfl_xor_sync(0xffffffffu, v, 1);
    return v;
}

__device__ __forceinline__ float sigm(float x) { return 1.0f / (1.0f + expf(-x)); }

// ---------------- Kernel 1: x_pre0 = seq @ W_ih0^T + (b_ih0 + b_hh0) ----------------
// seq[m=ei*16+bb] = batch[bb, ei+1, :]
__global__ void gemm_xpre(const float* __restrict__ batch,
                          const float* __restrict__ Wih0,
                          const float* __restrict__ bih0,
                          const float* __restrict__ bhh0) {
    const int BM = 64, BN = 64, BK = 32;
    __shared__ float Xs[BM][BK + 1];
    __shared__ float Ws[BN][BK + 1];

    int tid = threadIdx.x;            // 256 threads
    int nb = blockIdx.x * BN;
    int mb = blockIdx.y * BM;
    int tx = tid % 16, ty = tid / 16;

    float acc[4][4];
#pragma unroll
    for (int i = 0; i < 4; i++)
#pragma unroll
        for (int jj = 0; jj < 4; jj++) acc[i][jj] = 0.0f;

    for (int k0 = 0; k0 < 256; k0 += BK) {
#pragma unroll
        for (int i = 0; i < 8; i++) {
            int idx = tid + i * 256;
            int r = idx >> 5, kk = idx & 31;
            int m = mb + r;
            float v = 0.0f;
            if (m < NS) {
                int ei = m >> 4, bb = m & 15;
                v = batch[(size_t)bb * (64 * 256) + (size_t)(ei + 1) * 256 + (k0 + kk)];
            }
            Xs[r][kk] = v;
        }
#pragma unroll
        for (int i = 0; i < 8; i++) {
            int idx = tid + i * 256;
            int r = idx >> 5, kk = idx & 31;
            Ws[r][kk] = Wih0[(size_t)(nb + r) * 256 + (k0 + kk)];
        }
        __syncthreads();
#pragma unroll
        for (int kk = 0; kk < BK; kk++) {
            float xv[4], wv[4];
#pragma unroll
            for (int i = 0; i < 4; i++) xv[i] = Xs[ty * 4 + i][kk];
#pragma unroll
            for (int jj = 0; jj < 4; jj++) wv[jj] = Ws[tx * 4 + jj][kk];
#pragma unroll
            for (int i = 0; i < 4; i++)
#pragma unroll
                for (int jj = 0; jj < 4; jj++) acc[i][jj] += xv[i] * wv[jj];
        }
        __syncthreads();
    }
#pragma unroll
    for (int i = 0; i < 4; i++) {
        int m = mb + ty * 4 + i;
        if (m >= NS) continue;
#pragma unroll
        for (int jj = 0; jj < 4; jj++) {
            int n = nb + tx * 4 + jj;
            g_xpre[(size_t)m * FOURH + n] = acc[i][jj] + bih0[n] + bhh0[n];
        }
    }
}

// ---------------- Kernel 2: persistent sequential LSTM ----------------
// Iteration it (0..NS): layer0(step it) if it<NS, layer1(step it-1) if it>=1.
// Warp w of block b owns unit u = w*G + b; u<Hd -> layer0 unit j=u; Hd<=u<2Hd -> layer1 unit j=u-Hd.
__global__ __launch_bounds__(1024, 1)
void lstm_seq(const float* __restrict__ Whh0,
              const float* __restrict__ Wih1,
              const float* __restrict__ Whh1,
              const float* __restrict__ bih1,
              const float* __restrict__ bhh1,
              float* __restrict__ out,
              int G) {
    __shared__ float sh0[Hd];
    __shared__ float sh1[Hd];

    int tid  = threadIdx.x;
    int b    = blockIdx.x;
    int warp = tid >> 5;
    int lane = tid & 31;

    // zero the h ping-pong buffers (all blocks write identical zeros: benign)
    for (int i = tid; i < Hd; i += 1024) {
        g_h0[0][i] = 0.0f; g_h0[1][i] = 0.0f;
        g_h1[0][i] = 0.0f; g_h1[1][i] = 0.0f;
    }
    grid_barrier(G);

    int u = warp * G + b;
    bool isL0 = (u < Hd);
    bool isL1 = (u >= Hd) && (u < 2 * Hd);
    int j = isL0 ? u : (u - Hd);

    const float *w0i = nullptr, *w0f = nullptr, *w0g = nullptr, *w0o = nullptr;
    const float *wii = nullptr, *wif = nullptr, *wig = nullptr, *wio = nullptr;
    const float *whi = nullptr, *whf = nullptr, *whg = nullptr, *who = nullptr;
    float bi = 0.f, bf = 0.f, bg = 0.f, bo = 0.f;

    if (isL0) {
        w0i = Whh0 + (size_t)(0 * Hd + j) * Hd;
        w0f = Whh0 + (size_t)(1 * Hd + j) * Hd;
        w0g = Whh0 + (size_t)(2 * Hd + j) * Hd;
        w0o = Whh0 + (size_t)(3 * Hd + j) * Hd;
    } else if (isL1) {
        wii = Wih1 + (size_t)(0 * Hd + j) * Hd;
        wif = Wih1 + (size_t)(1 * Hd + j) * Hd;
        wig = Wih1 + (size_t)(2 * Hd + j) * Hd;
        wio = Wih1 + (size_t)(3 * Hd + j) * Hd;
        whi = Whh1 + (size_t)(0 * Hd + j) * Hd;
        whf = Whh1 + (size_t)(1 * Hd + j) * Hd;
        whg = Whh1 + (size_t)(2 * Hd + j) * Hd;
        who = Whh1 + (size_t)(3 * Hd + j) * Hd;
        bi = bih1[0 * Hd + j] + bhh1[0 * Hd + j];
        bf = bih1[1 * Hd + j] + bhh1[1 * Hd + j];
        bg = bih1[2 * Hd + j] + bhh1[2 * Hd + j];
        bo = bih1[3 * Hd + j] + bhh1[3 * Hd + j];
    }

    float c = 0.0f, h = 0.0f;   // cell/h state lives in registers for all 1008 steps

    for (int it = 0; it <= NS; ++it) {
        int rb = (it & 1) ^ 1;
        int wb = it & 1;

        // stage previous h vectors (volatile: L2-coherent) into smem
        {
            volatile const float* vh0 = g_h0[rb];
            volatile const float* vh1 = g_h1[rb];
            for (int i = tid; i < Hd; i += 1024) {
                sh0[i] = vh0[i];
                sh1[i] = vh1[i];
            }
        }
        __syncthreads();

        if (isL0 && it < NS) {
            const float* xp = g_xpre + (size_t)it * FOURH;
            float ai = 0.f, af = 0.f, ag = 0.f, ao = 0.f;
#pragma unroll 4
            for (int k = lane; k < Hd; k += 32) {
                float hv = sh0[k];
                ai += w0i[k] * hv;
                af += w0f[k] * hv;
                ag += w0g[k] * hv;
                ao += w0o[k] * hv;
            }
            ai = wred(ai); af = wred(af); ag = wred(ag); ao = wred(ao);
            float pi = xp[0 * Hd + j] + ai;
            float pf = xp[1 * Hd + j] + af;
            float pg = xp[2 * Hd + j] + ag;
            float po = xp[3 * Hd + j] + ao;
            c = sigm(pf) * c + sigm(pi) * tanhf(pg);
            h = sigm(po) * tanhf(c);
            if (lane == 0) ((volatile float*)g_h0[wb])[j] = h;
        }

        if (isL1 && it >= 1) {
            float ai = 0.f, af = 0.f, ag = 0.f, ao = 0.f;
#pragma unroll 4
            for (int k = lane; k < Hd; k += 32) {
                float hv = sh0[k];
                ai += wii[k] * hv;
                af += wif[k] * hv;
                ag += wig[k] * hv;
                ao += wio[k] * hv;
            }
#pragma unroll 4
            for (int k = lane; k < Hd; k += 32) {
                float hv = sh1[k];
                ai += whi[k] * hv;
                af += whf[k] * hv;
                ag += whg[k] * hv;
                ao += who[k] * hv;
            }
            ai = wred(ai) + bi; af = wred(af) + bf;
            ag = wred(ag) + bg; ao = wred(ao) + bo;
            c = sigm(af) * c + sigm(ai) * tanhf(ag);
            h = sigm(ao) * tanhf(c);
            if (lane == 0) ((volatile float*)g_h1[wb])[j] = h;
        }

        __threadfence();
        grid_barrier(G);
    }

    // out layout: [h0(1536) | h1(1536) | c0(1536) | c1(1536)]
    if (lane == 0) {
        if (isL0) { out[j] = h;          out[2 * Hd + j] = c; }
        if (isL1) { out[Hd + j] = h;     out[3 * Hd + j] = c; }
    }
}

// ---------------- launch ----------------
extern "C" void kernel_launch(void* const* d_in, const int* in_sizes, int n_in,
                              void* d_out, int out_size) {
    const float* batch = (const float*)d_in[0];
    const float* Wih0  = (const float*)d_in[1];
    const float* Whh0  = (const float*)d_in[2];
    const float* bih0  = (const float*)d_in[3];
    const float* bhh0  = (const float*)d_in[4];
    const float* Wih1  = (const float*)d_in[5];
    const float* Whh1  = (const float*)d_in[6];
    const float* bih1  = (const float*)d_in[7];
    const float* bhh1  = (const float*)d_in[8];
    float* out = (float*)d_out;

    int dev = 0;
    cudaGetDevice(&dev);
    int G = 0;
    cudaDeviceGetAttribute(&G, cudaDevAttrMultiProcessorCount, dev);
    if (G <= 0) G = 148;          // safe fallback
    if (G > 1024) G = 1024;       // paranoia clamp (mapping needs 32*G >= 3072 -> G >= 96)

    dim3 g1(FOURH / 64, (NS + 63) / 64);
    gemm_xpre<<<g1, 256>>>(batch, Wih0, bih0, bhh0);
    lstm_seq<<<G, 1024>>>(Whh0, Wih1, Whh1, bih1, bhh1, out, G);
}

// round 4
// speedup vs baseline: 7.8580x; 7.8580x over previous
#include <cuda_runtime.h>
#include <cuda_fp16.h>
#include <cstdint>

#define Hd    1536
#define FOURH 6144
#define NS    1008      // (T-1)*B = 63*16 sequential steps
#define CHUNKS 6        // 1536 / 256

// ---------------- static device scratch ----------------
__device__ float  g_xpre[(size_t)NS * FOURH];       // layer-0 input projection
__device__ __half g_Whh0h[(size_t)FOURH * Hd];      // fp16 weights, lane-permuted layout
__device__ __half g_Wih1h[(size_t)FOURH * Hd];
__device__ __half g_Whh1h[(size_t)FOURH * Hd];
__device__ float  g_h0[2][Hd];                      // ping-pong h, layer 0
__device__ float  g_h1[2][Hd];                      // ping-pong h, layer 1
__device__ float  g_pa[2][FOURH];                   // ping-pong partial (Wih1 . h0) per gate
__device__ unsigned int g_bar_count = 0;
__device__ unsigned int g_bar_gen   = 0;

// ---------------- software grid barrier ----------------
__device__ __forceinline__ void grid_barrier(int G) {
    __syncthreads();
    if (threadIdx.x == 0) {
        __threadfence();
        volatile unsigned int* genp = &g_bar_gen;
        unsigned int gen = *genp;
        unsigned int a = atomicAdd(&g_bar_count, 1u);
        if (a == (unsigned int)(G - 1)) {
            atomicExch(&g_bar_count, 0u);
            __threadfence();
            *genp = gen + 1u;
        } else {
            while (*genp == gen) { }
        }
    }
    __syncthreads();
}

__device__ __forceinline__ float wred(float v) {
    v += __shfl_xor_sync(0xffffffffu, v, 16);
    v += __shfl_xor_sync(0xffffffffu, v, 8);
    v += __shfl_xor_sync(0xffffffffu, v, 4);
    v += __shfl_xor_sync(0xffffffffu, v, 2);
    v += __shfl_xor_sync(0xffffffffu, v, 1);
    return v;
}

__device__ __forceinline__ float sigm(float x) { return 1.0f / (1.0f + expf(-x)); }

// ---------------- weight conversion fp32 -> fp16 (lane-permuted) ----------------
// Within each 1536-wide row, dst position p = chunk*256 + lane*8 + e holds
// src element chunk*256 + e*32 + lane. So a lane's uint4 load (8 halves) pairs
// with 8 conflict-free stride-32 smem reads of h.
__global__ void convert_weights(const float* __restrict__ Whh0,
                                const float* __restrict__ Wih1,
                                const float* __restrict__ Whh1) {
    size_t idx = (size_t)blockIdx.x * blockDim.x + threadIdx.x;
    const size_t per = (size_t)FOURH * Hd;
    if (idx >= 3 * per) return;
    int which = (int)(idx / per);
    size_t rem = idx % per;
    size_t r = rem / Hd;
    int p = (int)(rem % Hd);
    int chunk = p >> 8, q = p & 255, lane = q >> 3, e = q & 7;
    int srcp = chunk * 256 + e * 32 + lane;
    const float* src = (which == 0) ? Whh0 : (which == 1) ? Wih1 : Whh1;
    __half* dst = (which == 0) ? g_Whh0h : (which == 1) ? g_Wih1h : g_Whh1h;
    dst[r * Hd + p] = __float2half(src[r * Hd + srcp]);
}

// ---------------- Kernel: x_pre0 GEMM (unchanged) ----------------
__global__ void gemm_xpre(const float* __restrict__ batch,
                          const float* __restrict__ Wih0,
                          const float* __restrict__ bih0,
                          const float* __restrict__ bhh0) {
    const int BM = 64, BN = 64, BK = 32;
    __shared__ float Xs[BM][BK + 1];
    __shared__ float Ws[BN][BK + 1];

    int tid = threadIdx.x;
    int nb = blockIdx.x * BN;
    int mb = blockIdx.y * BM;
    int tx = tid % 16, ty = tid / 16;

    float acc[4][4];
#pragma unroll
    for (int i = 0; i < 4; i++)
#pragma unroll
        for (int jj = 0; jj < 4; jj++) acc[i][jj] = 0.0f;

    for (int k0 = 0; k0 < 256; k0 += BK) {
#pragma unroll
        for (int i = 0; i < 8; i++) {
            int idx = tid + i * 256;
            int r = idx >> 5, kk = idx & 31;
            int m = mb + r;
            float v = 0.0f;
            if (m < NS) {
                int ei = m >> 4, bb = m & 15;
                v = batch[(size_t)bb * (64 * 256) + (size_t)(ei + 1) * 256 + (k0 + kk)];
            }
            Xs[r][kk] = v;
        }
#pragma unroll
        for (int i = 0; i < 8; i++) {
            int idx = tid + i * 256;
            int r = idx >> 5, kk = idx & 31;
            Ws[r][kk] = Wih0[(size_t)(nb + r) * 256 + (k0 + kk)];
        }
        __syncthreads();
#pragma unroll
        for (int kk = 0; kk < BK; kk++) {
            float xv[4], wv[4];
#pragma unroll
            for (int i = 0; i < 4; i++) xv[i] = Xs[ty * 4 + i][kk];
#pragma unroll
            for (int jj = 0; jj < 4; jj++) wv[jj] = Ws[tx * 4 + jj][kk];
#pragma unroll
            for (int i = 0; i < 4; i++)
#pragma unroll
                for (int jj = 0; jj < 4; jj++) acc[i][jj] += xv[i] * wv[jj];
        }
        __syncthreads();
    }
#pragma unroll
    for (int i = 0; i < 4; i++) {
        int m = mb + ty * 4 + i;
        if (m >= NS) continue;
#pragma unroll
        for (int jj = 0; jj < 4; jj++) {
            int n = nb + tx * 4 + jj;
            g_xpre[(size_t)m * FOURH + n] = acc[i][jj] + bih0[n] + bhh0[n];
        }
    }
}

// ---------------- 4-row fp16 matvec (gate rows i,f,g,o of one unit) ----------------
// rows r_t = base + (t*Hd + j)*Hd; h staged in smem (fp32).
__device__ __forceinline__ void mv4(const __half* __restrict__ W, int j,
                                    const float* __restrict__ sh, int lane,
                                    float acc[4]) {
    const __half* r0 = W + (size_t)(0 * Hd + j) * Hd;
    const __half* r1 = W + (size_t)(1 * Hd + j) * Hd;
    const __half* r2 = W + (size_t)(2 * Hd + j) * Hd;
    const __half* r3 = W + (size_t)(3 * Hd + j) * Hd;
#pragma unroll
    for (int cc = 0; cc < CHUNKS; cc++) {
        int hb = cc * 256 + lane;
        float hv0 = sh[hb +   0], hv1 = sh[hb +  32];
        float hv2 = sh[hb +  64], hv3 = sh[hb +  96];
        float hv4 = sh[hb + 128], hv5 = sh[hb + 160];
        float hv6 = sh[hb + 192], hv7 = sh[hb + 224];
        int wb = cc * 256 + lane * 8;
#pragma unroll
        for (int t = 0; t < 4; t++) {
            const __half* rp = (t == 0) ? r0 : (t == 1) ? r1 : (t == 2) ? r2 : r3;
            uint4 u = *(const uint4*)(rp + wb);
            const __half2* p2 = (const __half2*)&u;
            float2 f0 = __half22float2(p2[0]);
            float2 f1 = __half22float2(p2[1]);
            float2 f2 = __half22float2(p2[2]);
            float2 f3 = __half22float2(p2[3]);
            acc[t] += f0.x * hv0 + f0.y * hv1 + f1.x * hv2 + f1.y * hv3
                    + f2.x * hv4 + f2.y * hv5 + f3.x * hv6 + f3.y * hv7;
        }
    }
}

// ---------------- persistent sequential LSTM ----------------
// Iteration it:
//   L0 warps (u in [0,1536)):      h0(it)          from h0(it-1)              [it < NS]
//   A  warps (u in [1536,3072)):   pa(it-1) = Wih1 . h0(it-1)                 [1 <= it <= NS]
//   B  warps (u in [3072,4608)):   finalize step it-2: Whh1 . h1(it-3) + pa   [it >= 2]
__global__ __launch_bounds__(1024, 1)
void lstm_seq(const float* __restrict__ bih1,
              const float* __restrict__ bhh1,
              float* __restrict__ out,
              int G) {
    __shared__ float sh0[Hd];
    __shared__ float sh1[Hd];

    int tid  = threadIdx.x;
    int b    = blockIdx.x;
    int warp = tid >> 5;
    int lane = tid & 31;

    for (int i = tid; i < Hd; i += 1024) {
        g_h0[0][i] = 0.0f; g_h0[1][i] = 0.0f;
        g_h1[0][i] = 0.0f; g_h1[1][i] = 0.0f;
    }
    for (int i = tid + b * 1024; i < FOURH; i += 1024 * G) {
        g_pa[0][i] = 0.0f; g_pa[1][i] = 0.0f;
    }
    grid_barrier(G);

    int u = warp * G + b;
    bool isL0 = (u < Hd);
    bool isA  = (u >= Hd)     && (u < 2 * Hd);
    bool isB  = (u >= 2 * Hd) && (u < 3 * Hd);
    int j = isL0 ? u : isA ? (u - Hd) : (u - 2 * Hd);

    float bi = 0.f, bf = 0.f, bg = 0.f, bo = 0.f;
    if (isB) {
        bi = bih1[0 * Hd + j] + bhh1[0 * Hd + j];
        bf = bih1[1 * Hd + j] + bhh1[1 * Hd + j];
        bg = bih1[2 * Hd + j] + bhh1[2 * Hd + j];
        bo = bih1[3 * Hd + j] + bhh1[3 * Hd + j];
    }

    float c = 0.0f, h = 0.0f;   // register-resident cell state

    for (int it = 0; it <= NS + 1; ++it) {
        int rp = (it + 1) & 1;   // read parity  == (it-1)&1
        int wp = it & 1;         // write parity

        {
            volatile const float* vh0 = g_h0[rp];
            volatile const float* vh1 = g_h1[rp];
            for (int i = tid; i < Hd; i += 1024) {
                sh0[i] = vh0[i];
                sh1[i] = vh1[i];
            }
        }
        __syncthreads();

        if (isL0) {
            if (it < NS) {
                float acc[4] = {0.f, 0.f, 0.f, 0.f};
                mv4(g_Whh0h, j, sh0, lane, acc);
                float pi = wred(acc[0]);
                float pf = wred(acc[1]);
                float pg = wred(acc[2]);
                float po = wred(acc[3]);
                const float* xp = g_xpre + (size_t)it * FOURH;
                pi += xp[0 * Hd + j];
                pf += xp[1 * Hd + j];
                pg += xp[2 * Hd + j];
                po += xp[3 * Hd + j];
                c = sigm(pf) * c + sigm(pi) * tanhf(pg);
                h = sigm(po) * tanhf(c);
                if (lane == 0) ((volatile float*)g_h0[wp])[j] = h;
            }
        } else if (isA) {
            if (it >= 1 && it <= NS) {
                float acc[4] = {0.f, 0.f, 0.f, 0.f};
                mv4(g_Wih1h, j, sh0, lane, acc);
                float pi = wred(acc[0]);
                float pf = wred(acc[1]);
                float pg = wred(acc[2]);
                float po = wred(acc[3]);
                if (lane == 0) {
                    volatile float* pa = g_pa[wp];
                    pa[0 * Hd + j] = pi;
                    pa[1 * Hd + j] = pf;
                    pa[2 * Hd + j] = pg;
                    pa[3 * Hd + j] = po;
                }
            }
        } else if (isB) {
            if (it >= 2) {
                float acc[4] = {0.f, 0.f, 0.f, 0.f};
                mv4(g_Whh1h, j, sh1, lane, acc);
                float pi = wred(acc[0]);
                float pf = wred(acc[1]);
                float pg = wred(acc[2]);
                float po = wred(acc[3]);
                if (lane == 0) {
                    volatile const float* pa = g_pa[rp];   // written at it-1
                    pi += pa[0 * Hd + j] + bi;
                    pf += pa[1 * Hd + j] + bf;
                    pg += pa[2 * Hd + j] + bg;
                    po += pa[3 * Hd + j] + bo;
                    c = sigm(pf) * c + sigm(pi) * tanhf(pg);
                    h = sigm(po) * tanhf(c);
                    ((volatile float*)g_h1[wp])[j] = h;
                }
            }
        }

        __threadfence();
        grid_barrier(G);
    }

    // out layout: [h0 | h1 | c0 | c1]
    if (lane == 0) {
        if (isL0) { out[j] = h;      out[2 * Hd + j] = c; }
        if (isB)  { out[Hd + j] = h; out[3 * Hd + j] = c; }
    }
}

// ---------------- launch ----------------
extern "C" void kernel_launch(void* const* d_in, const int* in_sizes, int n_in,
                              void* d_out, int out_size) {
    const float* batch = (const float*)d_in[0];
    const float* Wih0  = (const float*)d_in[1];
    const float* Whh0  = (const float*)d_in[2];
    const float* bih0  = (const float*)d_in[3];
    const float* bhh0  = (const float*)d_in[4];
    const float* Wih1  = (const float*)d_in[5];
    const float* Whh1  = (const float*)d_in[6];
    const float* bih1  = (const float*)d_in[7];
    const float* bhh1  = (const float*)d_in[8];
    float* out = (float*)d_out;

    int dev = 0;
    cudaGetDevice(&dev);
    int G = 0;
    cudaDeviceGetAttribute(&G, cudaDevAttrMultiProcessorCount, dev);
    if (G <= 0) G = 148;

    size_t total = (size_t)3 * FOURH * Hd;
    int cvt_blocks = (int)((total + 255) / 256);
    convert_weights<<<cvt_blocks, 256>>>(Whh0, Wih1, Whh1);

    dim3 g1(FOURH / 64, (NS + 63) / 64);
    gemm_xpre<<<g1, 256>>>(batch, Wih0, bih0, bhh0);

    lstm_seq<<<G, 1024>>>(bih1, bhh1, out, G);
}